// round 16
// baseline (speedup 1.0000x reference)
#include <cuda_runtime.h>
#include <math.h>

#define BATCH 8
#define H 1024
#define W 1024
#define NPIX (H*W)
#define TOPK 4096
#define CAP  262144
#define RS   84
#define RS2  (RS*RS)
#define NT   512
#define NBIN 4096
#define CCAP 6144
#define SORTN 8192
#define LISTCAP 512
#define WSCR 256
#define NSLICE 32

typedef unsigned long long ull;
typedef unsigned int uint;

// ---------------- scratch (zero-initialized at load; select_sort re-zeros each run) ----
__device__ ull      g_ckey[(size_t)BATCH*CAP];
__device__ int      g_ccnt[BATCH];
__device__ unsigned g_hist[BATCH*NBIN];
__device__ ull      g_sel[(size_t)BATCH*SORTN];
__device__ int      g_selcnt[BATCH];
__device__ int      g_binlo[BATCH];
__device__ int      g_flag[BATCH];
__device__ ull      g_comp[(size_t)BATCH*SORTN];

__device__ __forceinline__ int val_bin(unsigned u) {
    int bin = (u >= 0x3F000000u) ? (int)((u - 0x3F000000u) >> 11) : 0;
    return bin > NBIN-1 ? NBIN-1 : bin;
}

__device__ __forceinline__ float4 f4max(float4 a, float4 b) {
    return make_float4(fmaxf(a.x,b.x), fmaxf(a.y,b.y), fmaxf(a.z,b.z), fmaxf(a.w,b.w));
}

// ---------------- horizontal stages ----------------
template<int LO>
__device__ __forceinline__ void hmax_f4(const float* __restrict__ src,
                                        float* __restrict__ dst, int tid) {
    static_assert((LO & 3) == 2, "alignment");
    constexpr int Wd = RS - 2*LO;
    constexpr int NC = Wd/4;
    constexpr int YN = Wd + 4;
    for (int c = tid; c < YN*NC; c += NT) {
        int ry = (LO-2) + c / NC;
        int cx = LO + (c % NC)*4;
        const float* p = src + ry*RS + (cx-2);
        float4 A = *(const float4*)p;
        float4 B = *(const float4*)(p+4);
        float m12 = fmaxf(A.y, A.z);
        float m34 = fmaxf(A.w, B.x);
        float m56 = fmaxf(B.y, B.z);
        float* q = dst + ry*RS + cx;
        *(float2*)q     = make_float2(fmaxf(fmaxf(A.x, m12), m34),
                                      fmaxf(fmaxf(m12, m34), B.y));
        *(float2*)(q+2) = make_float2(fmaxf(fmaxf(A.z, m34), m56),
                                      fmaxf(fmaxf(m34, m56), B.w));
    }
}

template<int LO>
__device__ __forceinline__ void hmax_fm4(const float* __restrict__ sS,
                                         const unsigned char* __restrict__ sU,
                                         float* __restrict__ dst, int tid) {
    static_assert((LO & 3) == 2, "alignment");
    constexpr int Wd = RS - 2*LO;
    constexpr int NC = Wd/4;
    constexpr int YN = Wd + 4;
    for (int c = tid; c < YN*NC; c += NT) {
        int ry = (LO-2) + c / NC;
        int cx = LO + (c % NC)*4;
        int base = ry*RS + (cx-2);
        float4 A = *(const float4*)(sS + base);
        float4 B = *(const float4*)(sS + base + 4);
        uint u0 = *(const uint*)(sU + base);
        uint u1 = *(const uint*)(sU + base + 4);
        float v0 = (u0 & 0x000000FFu) ? 0.f : A.x;
        float v1 = (u0 & 0x0000FF00u) ? 0.f : A.y;
        float v2 = (u0 & 0x00FF0000u) ? 0.f : A.z;
        float v3 = (u0 & 0xFF000000u) ? 0.f : A.w;
        float v4 = (u1 & 0x000000FFu) ? 0.f : B.x;
        float v5 = (u1 & 0x0000FF00u) ? 0.f : B.y;
        float v6 = (u1 & 0x00FF0000u) ? 0.f : B.z;
        float v7 = (u1 & 0xFF000000u) ? 0.f : B.w;
        float m12 = fmaxf(v1, v2);
        float m34 = fmaxf(v3, v4);
        float m56 = fmaxf(v5, v6);
        float* q = dst + ry*RS + cx;
        *(float2*)q     = make_float2(fmaxf(fmaxf(v0, m12), m34),
                                      fmaxf(fmaxf(m12, m34), v5));
        *(float2*)(q+2) = make_float2(fmaxf(fmaxf(v2, m34), m56),
                                      fmaxf(fmaxf(m34, m56), v7));
    }
}

template<int LO>
__device__ __forceinline__ void hmax_b4(const unsigned char* __restrict__ src,
                                        unsigned char* __restrict__ dst, int tid) {
    static_assert((LO & 3) == 0, "alignment");
    constexpr int Wd = RS - 2*LO;
    constexpr int NC = Wd/4;
    constexpr int YN = Wd + 4;
    for (int c = tid; c < YN*NC; c += NT) {
        int ry = (LO-2) + c / NC;
        int cx = LO + (c % NC)*4;
        int base = ry*RS + cx;
        uint W0 = *(const uint*)(src + base - 4);
        uint W1 = *(const uint*)(src + base);
        uint W2 = *(const uint*)(src + base + 4);
        uint v1 = __byte_perm(W0, W1, 0x5432);
        uint v2 = __byte_perm(W0, W1, 0x6543);
        uint v4 = __byte_perm(W1, W2, 0x4321);
        uint v5 = __byte_perm(W1, W2, 0x5432);
        *(uint*)(dst + base) = v1 | v2 | W1 | v4 | v5;
    }
}

#define VLOAD8_F4(tp) \
    float4 t0 = *(const float4*)(tp); \
    float4 t1 = *(const float4*)((tp) + RS); \
    float4 t2 = *(const float4*)((tp) + 2*RS); \
    float4 t3 = *(const float4*)((tp) + 3*RS); \
    float4 t4 = *(const float4*)((tp) + 4*RS); \
    float4 t5 = *(const float4*)((tp) + 5*RS); \
    float4 t6 = *(const float4*)((tp) + 6*RS); \
    float4 t7 = *(const float4*)((tp) + 7*RS); \
    float4 m12 = f4max(t1,t2), m34 = f4max(t3,t4), m56 = f4max(t5,t6); \
    float4 o[4]; \
    o[0] = f4max(f4max(t0,m12),m34); \
    o[1] = f4max(f4max(m12,m34),t5); \
    o[2] = f4max(f4max(t2,m34),m56); \
    o[3] = f4max(f4max(m34,m56),t7);

__global__ __launch_bounds__(NT, 3) void nms_fused(const float* __restrict__ S) {
    extern __shared__ float sh[];
    float* sS = sh;
    float* sT = sh + RS2;
    unsigned char* sTb = (unsigned char*)sT;
    unsigned char* sM = (unsigned char*)(sh + 2*RS2);
    unsigned char* sU = sM + RS2;
    ull* sList = (ull*)(sM + 2*RS2);
    __shared__ int s_cnt, s_base;

    int tid = threadIdx.x;
    int b = blockIdx.z;
    int tx0 = blockIdx.x*64 - 10, ty0 = blockIdx.y*64 - 10;
    const float* img = S + (size_t)b*NPIX;

    bool interior = (blockIdx.x >= 1) & (blockIdx.x <= 14) &
                    (blockIdx.y >= 1) & (blockIdx.y <= 14);
    if (interior) {
        const float* rowbase = img + (size_t)ty0*W + (tx0 - 2);
        for (int i = tid; i < 84*22; i += NT) {
            int ry = i / 22, k = i - ry*22;
            float4 v = __ldg((const float4*)(rowbase + (size_t)ry*W) + k);
            int rx0 = 4*k - 2;
            float* q = sS + ry*RS + rx0;
            if (k > 0)  *(float2*)q     = make_float2(v.x, v.y);
            if (k < 21) *(float2*)(q+2) = make_float2(v.z, v.w);
        }
    } else {
        for (int i = tid; i < RS2; i += NT) {
            int ry = i/RS, rx = i - ry*RS;
            int gx = tx0+rx, gy = ty0+ry;
            bool in = ((unsigned)gx < W) & ((unsigned)gy < H);
            sS[i] = in ? __ldg(img + gy*W + gx) : 0.f;
        }
    }
    if (tid == 0) s_cnt = 0;
    __syncthreads();

    // ---- stage 1
    hmax_f4<2>(sS, sT, tid); __syncthreads();
    {
        constexpr int NCX = 21, NRY = 20;
        for (int c = tid; c < NCX*NRY; c += NT) {
            int rx0 = (c % NCX)*4;
            int ry0 = 2 + (c / NCX)*4;
            const float* tp = sT + (ry0-2)*RS + rx0;
            VLOAD8_F4(tp);
            int gx = tx0 + rx0;
            bool in0 = (unsigned)(gx+0) < W, in1 = (unsigned)(gx+1) < W;
            bool in2 = (unsigned)(gx+2) < W, in3 = (unsigned)(gx+3) < W;
            #pragma unroll
            for (int r = 0; r < 4; r++) {
                int idx = (ry0+r)*RS + rx0;
                float4 s = *(const float4*)(sS + idx);
                bool iny = (unsigned)(ty0+ry0+r) < H;
                uchar4 mm;
                mm.x = (unsigned char)(iny & in0 & (s.x == o[r].x));
                mm.y = (unsigned char)(iny & in1 & (s.y == o[r].y));
                mm.z = (unsigned char)(iny & in2 & (s.z == o[r].z));
                mm.w = (unsigned char)(iny & in3 & (s.w == o[r].w));
                *(uchar4*)(sM + idx) = mm;
            }
        }
    }
    __syncthreads();

    // ---- stage 2
    hmax_b4<4>(sM, sTb, tid); __syncthreads();
    {
        constexpr int NCX = 19, NRY = 19;
        for (int c = tid; c < NCX*NRY; c += NT) {
            int rx0 = 4 + (c % NCX)*4;
            int ry0 = 4 + (c / NCX)*4;
            const unsigned char* tp = sTb + (ry0-2)*RS + rx0;
            uint t0 = *(const uint*)(tp);
            uint t1 = *(const uint*)(tp + RS);
            uint t2 = *(const uint*)(tp + 2*RS);
            uint t3 = *(const uint*)(tp + 3*RS);
            uint t4 = *(const uint*)(tp + 4*RS);
            uint t5 = *(const uint*)(tp + 5*RS);
            uint t6 = *(const uint*)(tp + 6*RS);
            uint t7 = *(const uint*)(tp + 7*RS);
            uint m12 = t1|t2, m34 = t3|t4, m56 = t5|t6;
            unsigned char* up = sU + ry0*RS + rx0;
            *(uint*)(up)        = t0|m12|m34;
            *(uint*)(up + RS)   = m12|m34|t5;
            *(uint*)(up + 2*RS) = t2|m34|m56;
            *(uint*)(up + 3*RS) = m34|m56|t7;
        }
    }
    __syncthreads();

    // ---- stage 3
    hmax_fm4<6>(sS, sU, sT, tid); __syncthreads();
    {
        constexpr int NCX = 19, NRY = 18;
        for (int c = tid; c < NCX*NRY; c += NT) {
            int rx0 = 4 + (c % NCX)*4;
            int ry0 = 6 + (c / NCX)*4;
            const float* tp = sT + (ry0-2)*RS + rx0;
            VLOAD8_F4(tp);
            int gx = tx0 + rx0;
            bool in0 = (unsigned)(gx+0) < W, in1 = (unsigned)(gx+1) < W;
            bool in2 = (unsigned)(gx+2) < W, in3 = (unsigned)(gx+3) < W;
            #pragma unroll
            for (int r = 0; r < 4; r++) {
                int idx = (ry0+r)*RS + rx0;
                float4 s = *(const float4*)(sS + idx);
                uint u = *(const uint*)(sU + idx);
                uchar4 pm = *(const uchar4*)(sM + idx);
                bool iny = (unsigned)(ty0+ry0+r) < H;
                bool u0 = (u & 0x000000FFu) != 0, u1 = (u & 0x0000FF00u) != 0;
                bool u2 = (u & 0x00FF0000u) != 0, u3 = (u & 0xFF000000u) != 0;
                uchar4 mm;
                mm.x = (unsigned char)(iny & in0 & ((pm.x != 0) | (!u0 & (s.x == o[r].x))));
                mm.y = (unsigned char)(iny & in1 & ((pm.y != 0) | (!u1 & (s.y == o[r].y))));
                mm.z = (unsigned char)(iny & in2 & ((pm.z != 0) | (!u2 & (s.z == o[r].z))));
                mm.w = (unsigned char)(iny & in3 & ((pm.w != 0) | (!u3 & (s.w == o[r].w))));
                *(uchar4*)(sM + idx) = mm;
            }
        }
    }
    __syncthreads();

    // ---- stage 4
    hmax_b4<8>(sM, sTb, tid); __syncthreads();
    {
        constexpr int NCX = 17, NRY = 17;
        for (int c = tid; c < NCX*NRY; c += NT) {
            int rx0 = 8 + (c % NCX)*4;
            int ry0 = 8 + (c / NCX)*4;
            const unsigned char* tp = sTb + (ry0-2)*RS + rx0;
            uint t0 = *(const uint*)(tp);
            uint t1 = *(const uint*)(tp + RS);
            uint t2 = *(const uint*)(tp + 2*RS);
            uint t3 = *(const uint*)(tp + 3*RS);
            uint t4 = *(const uint*)(tp + 4*RS);
            uint t5 = *(const uint*)(tp + 5*RS);
            uint t6 = *(const uint*)(tp + 6*RS);
            uint t7 = *(const uint*)(tp + 7*RS);
            uint m12 = t1|t2, m34 = t3|t4, m56 = t5|t6;
            unsigned char* up = sU + ry0*RS + rx0;
            *(uint*)(up)        = t0|m12|m34;
            *(uint*)(up + RS)   = m12|m34|t5;
            *(uint*)(up + 2*RS) = t2|m34|m56;
            *(uint*)(up + 3*RS) = m34|m56|t7;
        }
    }
    __syncthreads();

    // ---- stage 5
    hmax_fm4<10>(sS, sU, sT, tid); __syncthreads();
    {
        constexpr int NCX = 17, NRY = 16;
        for (int c = tid; c < NCX*NRY; c += NT) {
            int rx0 = 8 + (c % NCX)*4;
            int ry0 = 10 + (c / NCX)*4;
            const float* tp = sT + (ry0-2)*RS + rx0;
            VLOAD8_F4(tp);
            #pragma unroll
            for (int r = 0; r < 4; r++) {
                int idx = (ry0+r)*RS + rx0;
                float4 s = *(const float4*)(sS + idx);
                uint u = *(const uint*)(sU + idx);
                uchar4 pm = *(const uchar4*)(sM + idx);
                int gy = ty0 + ry0 + r;
                bool by = (gy < 2) | (gy >= H-2);
                float sv[4] = {s.x, s.y, s.z, s.w};
                float ov[4] = {o[r].x, o[r].y, o[r].z, o[r].w};
                unsigned char uv[4] = {(unsigned char)(u & 0xFF),
                                       (unsigned char)((u >> 8) & 0xFF),
                                       (unsigned char)((u >> 16) & 0xFF),
                                       (unsigned char)((u >> 24) & 0xFF)};
                unsigned char pv[4] = {pm.x, pm.y, pm.z, pm.w};
                #pragma unroll
                for (int lx = 0; lx < 4; lx++) {
                    int rx = rx0 + lx;
                    if (rx < 10 || rx >= 74) continue;
                    bool ux = uv[lx] != 0;
                    bool nw = !ux && (sv[lx] == ov[lx]);
                    bool m = (pv[lx] != 0) || nw;
                    int gx = tx0 + rx;
                    bool border = (gx < 2) | (gx >= W-2) | by;
                    if (m & !border & (sv[lx] > 0.f)) {
                        unsigned ub = __float_as_uint(sv[lx]);
                        atomicAdd(&g_hist[b*NBIN + val_bin(ub)], 1u);
                        ull key = ((ull)ub << 32) |
                                  (ull)(0xFFFFFFFFu - (unsigned)(gy*W + gx));
                        int p = atomicAdd(&s_cnt, 1);
                        if (p < LISTCAP) sList[p] = key;
                        else {
                            int q = atomicAdd(&g_ccnt[b], 1);
                            if (q < CAP) g_ckey[(size_t)b*CAP + q] = key;
                        }
                    }
                }
            }
        }
        __syncthreads();
        if (tid == 0) {
            int c2 = s_cnt < LISTCAP ? s_cnt : LISTCAP;
            s_base = atomicAdd(&g_ccnt[b], c2);
            s_cnt = c2;
        }
        __syncthreads();
        int c2 = s_cnt, base = s_base;
        for (int i = tid; i < c2; i += NT) {
            int q = base + i;
            if (q < CAP) g_ckey[(size_t)b*CAP + q] = sList[i];
        }
    }
}

// ---------------- prefilter: chip-parallel threshold + compaction ----------------
__global__ void __launch_bounds__(256) prefilter_kernel() {
    __shared__ unsigned swsuf[9];
    __shared__ int s_binlo, s_flag;
    __shared__ unsigned s_sel;
    int b = blockIdx.y, slice = blockIdx.x;
    int tid = threadIdx.x, lane = tid & 31, warp = tid >> 5;

    if (tid == 0) { s_binlo = -1; s_flag = 0; s_sel = 0; swsuf[8] = 0; }
    __syncthreads();

    // each thread owns 16 bins
    unsigned h[16];
    const uint4* hp = (const uint4*)(g_hist + b*NBIN) + tid*4;
    #pragma unroll
    for (int q = 0; q < 4; q++) {
        uint4 w = hp[q];
        h[q*4+0]=w.x; h[q*4+1]=w.y; h[q*4+2]=w.z; h[q*4+3]=w.w;
    }
    unsigned tt = 0;
    #pragma unroll
    for (int j = 0; j < 16; j++) tt += h[j];
    unsigned v = tt;
    #pragma unroll
    for (int o = 1; o < 32; o <<= 1) {
        unsigned t2 = __shfl_down_sync(0xFFFFFFFFu, v, o);
        if (lane + o < 32) v += t2;
    }
    if (lane == 0) swsuf[warp] = v;
    __syncthreads();
    if (warp == 0 && lane < 8) {
        unsigned wv = swsuf[lane];
        #pragma unroll
        for (int o = 1; o < 8; o <<= 1) {
            unsigned t2 = __shfl_down_sync(0x000000FFu, wv, o);
            if (lane + o < 8) wv += t2;
        }
        swsuf[lane] = wv;
    }
    __syncthreads();
    unsigned total = swsuf[0];
    unsigned tail = (v - tt) + swsuf[warp+1];
    unsigned need = total < (unsigned)TOPK ? total : (unsigned)TOPK;

    if (total > (unsigned)CCAP) {
        unsigned running = tail;
        #pragma unroll
        for (int j = 15; j >= 0; j--) {
            unsigned sj = running + h[j];
            if (sj >= need && running < need) { s_binlo = tid*16+j; s_sel = sj; }
            running = sj;
        }
    } else {
        if (tid == 0) s_flag = 1;
    }
    __syncthreads();
    int binlo = s_binlo;
    if ((binlo <= 0 || s_sel > (unsigned)CCAP) && !s_flag) s_flag = 1;
    #pragma unroll
    for (int j = 0; j < 16; j++)
        if (tid*16+j >= binlo && binlo > 0 && h[j] > (unsigned)WSCR) s_flag = 1;
    __syncthreads();

    if (s_flag) {
        if (slice == 0 && tid == 0) g_flag[b] = 1;
        return;
    }
    if (slice == 0 && tid == 0) { g_flag[b] = 0; g_binlo[b] = binlo; }

    // scan slice of candidates, compact survivors
    int n = g_ccnt[b]; if (n > CAP) n = CAP;
    const ull* ck = g_ckey + (size_t)b*CAP;
    unsigned ulo = 0x3F000000u + ((unsigned)binlo << 11);
    int npair = n >> 1;
    int chunk = (npair + NSLICE - 1) / NSLICE;
    int lo = slice*chunk;
    int hi = min(npair, lo + chunk);
    const ulonglong2* ck2 = (const ulonglong2*)ck;
    for (int bi = lo; bi < hi; bi += 256) {
        int i = bi + tid;
        bool valid = i < hi;
        ulonglong2 kp = valid ? ck2[i] : make_ulonglong2(0,0);
        #pragma unroll
        for (int s2 = 0; s2 < 2; s2++) {
            ull kk = s2 ? kp.y : kp.x;
            bool take = valid && ((unsigned)(kk >> 32) >= ulo);
            unsigned m = __ballot_sync(0xFFFFFFFFu, take);
            if (m) {
                int leader = __ffs(m) - 1;
                int base = 0;
                if (lane == leader) base = atomicAdd(&g_selcnt[b], __popc(m));
                base = __shfl_sync(0xFFFFFFFFu, base, leader);
                if (take) {
                    int p = base + __popc(m & ((1u << lane) - 1));
                    if (p < SORTN) g_sel[(size_t)b*SORTN + p] = kk;
                }
            }
        }
    }
    if (slice == NSLICE-1 && tid == 0 && (n & 1)) {
        ull kk = ck[n-1];
        if ((unsigned)(kk >> 32) >= ulo) {
            int p = atomicAdd(&g_selcnt[b], 1);
            if (p < SORTN) g_sel[(size_t)b*SORTN + p] = kk;
        }
    }
}

// ---------------- sort + output + state reset ----------------
__global__ void __launch_bounds__(1024) select_sort() {
    extern __shared__ char smraw[];
    unsigned* hist = (unsigned*)smraw;
    unsigned* suf  = hist + NBIN;
    unsigned* off  = suf + NBIN;
    ull* keys      = (ull*)(off + NBIN);
    ull* scratch   = keys + SORTN;

    __shared__ int s_binhi;
    __shared__ unsigned s_wsuf[33];
    __shared__ ull s_hi;
    __shared__ int s_need2, s_bin2, s_cnt2;

    int b = blockIdx.x, tid = threadIdx.x;
    int lane = tid & 31, warp = tid >> 5;
    int n = g_ccnt[b]; if (n > CAP) n = CAP;
    int cnt = g_selcnt[b]; if (cnt > SORTN) cnt = SORTN;
    int flag = g_flag[b];
    int binlo = g_binlo[b];
    const ull* ck = g_ckey + (size_t)b*CAP;

    if (tid == 0) { s_binhi = 0; s_wsuf[32] = 0; }
    __syncthreads();

    if (tid == 0) { g_ccnt[b] = 0; g_selcnt[b] = 0; }   // reset for next replay

    uint4 hv = *((const uint4*)(g_hist + b*NBIN) + tid);
    *((uint4*)(g_hist + b*NBIN) + tid) = make_uint4(0,0,0,0);   // reset
    unsigned h[4] = {hv.x, hv.y, hv.z, hv.w};
    unsigned l[4];
    l[3] = h[3]; l[2] = h[2]+l[3]; l[1] = h[1]+l[2]; l[0] = h[0]+l[1];
    #pragma unroll
    for (int k = 0; k < 4; k++) hist[tid*4+k] = h[k];
    int mybh = -1;
    #pragma unroll
    for (int k = 0; k < 4; k++) if (h[k]) mybh = tid*4+k;
    if (mybh >= 0) atomicMax(&s_binhi, mybh);

    unsigned v = l[0];
    #pragma unroll
    for (int o = 1; o < 32; o <<= 1) {
        unsigned t = __shfl_down_sync(0xFFFFFFFFu, v, o);
        if (lane + o < 32) v += t;
    }
    if (lane == 0) s_wsuf[warp] = v;
    __syncthreads();
    if (warp == 0) {
        unsigned wv = s_wsuf[lane];
        #pragma unroll
        for (int o = 1; o < 32; o <<= 1) {
            unsigned t = __shfl_down_sync(0xFFFFFFFFu, wv, o);
            if (lane + o < 32) wv += t;
        }
        s_wsuf[lane] = wv;
    }
    __syncthreads();
    unsigned tail = (v - l[0]) + s_wsuf[warp+1];
    #pragma unroll
    for (int k = 0; k < 4; k++) suf[tid*4+k] = l[k] + tail;
    __syncthreads();
    #pragma unroll
    for (int k = 0; k < 4; k++) {
        int bin = tid*4+k;
        off[bin] = (bin < NBIN-1) ? suf[bin+1] : 0u;
    }
    __syncthreads();

    if (!flag) {
        // scatter preselected keys into bin-ordered smem positions
        for (int i = tid; i < cnt; i += 1024) {
            ull kk = g_sel[(size_t)b*SORTN + i];
            int bin = val_bin((unsigned)(kk >> 32));
            unsigned pos = atomicAdd(&off[bin], 1u);
            if (pos < (unsigned)SORTN) keys[pos] = kk;
        }
        __syncthreads();
        for (int i = cnt + tid; i < TOPK; i += 1024)
            keys[i] = (ull)(0xFFFFFFFFu - (unsigned)i);
        __syncthreads();

        ull* wscr = scratch + warp*WSCR;
        int binhi = s_binhi;
        for (int bin = binlo + warp; bin <= binhi; bin += 32) {
            int c = (int)hist[bin];
            if (c < 2) continue;
            int start = (int)off[bin] - c;
            if (start >= TOPK) continue;
            int P = 1; while (P < c) P <<= 1;
            for (int i = lane; i < P; i += 32) wscr[i] = (i < c) ? keys[start+i] : 0ULL;
            __syncwarp();
            for (int k2 = 2; k2 <= P; k2 <<= 1) {
                for (int j = k2 >> 1; j > 0; j >>= 1) {
                    for (int t = lane; t < P; t += 32) {
                        int p = t ^ j;
                        if (p > t) {
                            ull a = wscr[t], c2 = wscr[p];
                            bool desc = ((t & k2) == 0);
                            if ((a < c2) == desc) { wscr[t] = c2; wscr[p] = a; }
                        }
                    }
                    __syncwarp();
                }
            }
            for (int i = lane; i < c; i += 32) keys[start+i] = wscr[i];
            __syncwarp();
        }
        __syncthreads();
        for (int i = tid; i < TOPK; i += 1024)
            g_comp[(size_t)b*SORTN + i] = keys[i];
        return;
    }

    // ---- fallback: exact 6-level radix select + bitonic ----
    unsigned* fhist = suf;
    if (tid == 0) { s_hi = 0ull; s_need2 = TOPK; }
    __syncthreads();
    const int shifts[6] = {53, 42, 32, 21, 10, 0};
    const int nbits [6] = {11, 11, 10, 11, 11, 10};
    for (int lvl = 0; lvl < 6; lvl++) {
        int nb = nbits[lvl], sh2 = shifts[lvl], nbin = 1 << nb;
        for (int i = tid; i < nbin; i += 1024) fhist[i] = 0;
        __syncthreads();
        ull hi = s_hi;
        for (int i = tid; i < n; i += 1024) {
            ull c = ck[i];
            if ((c >> (sh2 + nb)) == hi)
                atomicAdd(&fhist[(unsigned)((c >> sh2) & (ull)(nbin-1))], 1u);
        }
        __syncthreads();
        for (int o = 1; o < nbin; o <<= 1) {
            unsigned a0 = 0, a1 = 0;
            int i0 = tid, i1 = tid + 1024;
            if (i0 < nbin) a0 = fhist[i0] + ((i0+o < nbin) ? fhist[i0+o] : 0u);
            if (i1 < nbin) a1 = fhist[i1] + ((i1+o < nbin) ? fhist[i1+o] : 0u);
            __syncthreads();
            if (i0 < nbin) fhist[i0] = a0;
            if (i1 < nbin) fhist[i1] = a1;
            __syncthreads();
        }
        if (tid == 0) s_bin2 = -1;
        __syncthreads();
        int need2 = s_need2;
        for (int i = tid; i < nbin; i += 1024) {
            unsigned Si = fhist[i];
            unsigned Sn = (i+1 < nbin) ? fhist[i+1] : 0u;
            if (Si >= (unsigned)need2 && Sn < (unsigned)need2) s_bin2 = i;
        }
        __syncthreads();
        if (tid == 0) {
            int bin = s_bin2;
            if (bin < 0) { bin = 0; s_need2 = (int)fhist[0]; }
            else {
                unsigned above = (bin+1 < nbin) ? fhist[bin+1] : 0u;
                s_need2 = s_need2 - (int)above;
            }
            s_hi = (s_hi << nb) | (ull)(unsigned)bin;
        }
        __syncthreads();
    }
    ull T = s_hi;
    if (tid == 0) s_cnt2 = 0;
    __syncthreads();
    for (int i = tid; i < n; i += 1024) {
        ull c = ck[i];
        if (c >= T) {
            int p = atomicAdd(&s_cnt2, 1);
            if (p < TOPK) keys[p] = c;
        }
    }
    __syncthreads();
    int cnt2 = s_cnt2; if (cnt2 > TOPK) cnt2 = TOPK;
    for (int i = tid; i < TOPK; i += 1024)
        if (i >= cnt2) keys[i] = (ull)(0xFFFFFFFFu - (unsigned)i);
    __syncthreads();
    for (int k = 2; k <= TOPK; k <<= 1) {
        for (int j = k >> 1; j > 0; j >>= 1) {
            for (int t = tid; t < TOPK; t += 1024) {
                int p = t ^ j;
                if (p > t) {
                    ull a = keys[t], c2 = keys[p];
                    bool asc = ((t & k) == 0);
                    if ((a > c2) == asc) { keys[t] = c2; keys[p] = a; }
                }
            }
            __syncthreads();
        }
    }
    for (int i = tid; i < TOPK; i += 1024)
        g_comp[(size_t)b*SORTN + i] = keys[TOPK-1-i];
}

// ---------------- refinement ----------------
__device__ __forceinline__ float bil_tap(const float* img, float xf, float yf, float wgt) {
    bool valid = (xf >= 0.f) & (xf < (float)W) & (yf >= 0.f) & (yf < (float)H);
    int xc = (int)fminf(fmaxf(xf, 0.f), (float)(W-1));
    int yc = (int)fminf(fmaxf(yf, 0.f), (float)(H-1));
    float s = valid ? img[yc*W + xc] : 0.f;
    return s * wgt;
}

__global__ void refine_kernel(const float* __restrict__ S, float* __restrict__ out) {
    int g = blockIdx.x * blockDim.x + threadIdx.x;
    if (g >= BATCH*TOPK) return;
    int b = g / TOPK;
    int i = g - b*TOPK;
    ull key = g_comp[(size_t)b*SORTN + i];
    int idx = (int)(0xFFFFFFFFu - (unsigned)(key & 0xFFFFFFFFull));
    int ix = idx & (W-1), iy = idx >> 10;
    const float* img = S + (size_t)b*NPIX;

    float v[25];
    float mx = -1e30f;
    #pragma unroll
    for (int dy = 0; dy < 5; dy++) {
        int y = iy + dy - 2;
        #pragma unroll
        for (int dx = 0; dx < 5; dx++) {
            int x = ix + dx - 2;
            float val = (y >= 0 && y < H && x >= 0 && x < W) ? __ldg(img + y*W + x) : 0.f;
            v[dy*5 + dx] = val;
            mx = fmaxf(mx, val);
        }
    }
    float e[25];
    float S0 = 0.f, Sx = 0.f, Sy = 0.f;
    #pragma unroll
    for (int p = 0; p < 25; p++) {
        float ee = expf((v[p] - mx) * 10.0f);
        e[p] = ee;
        S0 += ee;
        Sx += ee * (float)(p % 5 - 2);
        Sy += ee * (float)(p / 5 - 2);
    }
    float rx = Sx / S0, ry = Sy / S0;
    float disp = 0.f;
    #pragma unroll
    for (int p = 0; p < 25; p++) {
        float ddx = ((float)(p % 5 - 2) - rx) * 0.5f;
        float ddy = ((float)(p / 5 - 2) - ry) * 0.5f;
        disp += e[p] * (ddx*ddx + ddy*ddy);
    }
    disp /= S0;

    float kx = ((float)ix + rx) / (float)(W-1) * 2.f - 1.f;
    float ky = ((float)iy + ry) / (float)(H-1) * 2.f - 1.f;

    float px = (kx + 1.f) * 0.5f * (float)(W-1);
    float py = (ky + 1.f) * 0.5f * (float)(H-1);
    float x0 = floorf(px), y0 = floorf(py);
    float wx1 = px - x0, wx0 = 1.f - wx1;
    float wy1 = py - y0, wy0 = 1.f - wy1;
    float score = bil_tap(img, x0,     y0,     wx0*wy0)
                + bil_tap(img, x0+1.f, y0,     wx1*wy0)
                + bil_tap(img, x0,     y0+1.f, wx0*wy1)
                + bil_tap(img, x0+1.f, y0+1.f, wx1*wy1);

    out[2*g + 0] = kx;
    out[2*g + 1] = ky;
    out[BATCH*TOPK*2 + g] = score;
    out[BATCH*TOPK*3 + g] = disp;
}

// ---------------- launch ----------------
extern "C" void kernel_launch(void* const* d_in, const int* in_sizes, int n_in,
                              void* d_out, int out_size) {
    const float* S = (const float*)d_in[0];
    float* out = (float*)d_out;

    const int nms_smem = 2*RS2*sizeof(float) + 2*RS2 + LISTCAP*sizeof(ull);
    const int sel_smem = 3*NBIN*sizeof(unsigned) + SORTN*sizeof(ull) + 32*WSCR*sizeof(ull);
    static int attr_set = 0;
    if (!attr_set) {
        cudaFuncSetAttribute(nms_fused, cudaFuncAttributeMaxDynamicSharedMemorySize, nms_smem);
        cudaFuncSetAttribute(select_sort, cudaFuncAttributeMaxDynamicSharedMemorySize, sel_smem);
        attr_set = 1;
    }

    dim3 grid(16, 16, 8);
    nms_fused<<<grid, NT, nms_smem>>>(S);
    prefilter_kernel<<<dim3(NSLICE, BATCH), 256>>>();
    select_sort<<<BATCH, 1024, sel_smem>>>();
    refine_kernel<<<(BATCH*TOPK + 127) / 128, 128>>>(S, out);
}

// round 17
// speedup vs baseline: 1.0459x; 1.0459x over previous
#include <cuda_runtime.h>
#include <math.h>

#define BATCH 8
#define H 1024
#define W 1024
#define NPIX (H*W)
#define TOPK 4096
#define CAP  262144
#define RS   84
#define RS2  (RS*RS)
#define NT   512
#define NBIN 4096
#define CCAP 6144
#define SORTN 8192
#define LISTCAP 512
#define WSCR 256
#define NSLICE 32

typedef unsigned long long ull;
typedef unsigned int uint;

// ---------------- scratch (zero-initialized at load; binsort re-zeros each run) ----
__device__ ull      g_ckey[(size_t)BATCH*CAP];
__device__ int      g_ccnt[BATCH];
__device__ unsigned g_hist[BATCH*NBIN];
__device__ unsigned g_binpos[BATCH*NBIN];
__device__ int      g_binlo[BATCH];
__device__ int      g_flag[BATCH];
__device__ ull      g_comp[(size_t)BATCH*SORTN];

__device__ __forceinline__ int val_bin(unsigned u) {
    int bin = (u >= 0x3F000000u) ? (int)((u - 0x3F000000u) >> 11) : 0;
    return bin > NBIN-1 ? NBIN-1 : bin;
}

__device__ __forceinline__ float4 f4max(float4 a, float4 b) {
    return make_float4(fmaxf(a.x,b.x), fmaxf(a.y,b.y), fmaxf(a.z,b.z), fmaxf(a.w,b.w));
}

// ---------------- horizontal stages ----------------
template<int LO>
__device__ __forceinline__ void hmax_f4(const float* __restrict__ src,
                                        float* __restrict__ dst, int tid) {
    static_assert((LO & 3) == 2, "alignment");
    constexpr int Wd = RS - 2*LO;
    constexpr int NC = Wd/4;
    constexpr int YN = Wd + 4;
    for (int c = tid; c < YN*NC; c += NT) {
        int ry = (LO-2) + c / NC;
        int cx = LO + (c % NC)*4;
        const float* p = src + ry*RS + (cx-2);
        float4 A = *(const float4*)p;
        float4 B = *(const float4*)(p+4);
        float m12 = fmaxf(A.y, A.z);
        float m34 = fmaxf(A.w, B.x);
        float m56 = fmaxf(B.y, B.z);
        float* q = dst + ry*RS + cx;
        *(float2*)q     = make_float2(fmaxf(fmaxf(A.x, m12), m34),
                                      fmaxf(fmaxf(m12, m34), B.y));
        *(float2*)(q+2) = make_float2(fmaxf(fmaxf(A.z, m34), m56),
                                      fmaxf(fmaxf(m34, m56), B.w));
    }
}

template<int LO>
__device__ __forceinline__ void hmax_fm4(const float* __restrict__ sS,
                                         const unsigned char* __restrict__ sU,
                                         float* __restrict__ dst, int tid) {
    static_assert((LO & 3) == 2, "alignment");
    constexpr int Wd = RS - 2*LO;
    constexpr int NC = Wd/4;
    constexpr int YN = Wd + 4;
    for (int c = tid; c < YN*NC; c += NT) {
        int ry = (LO-2) + c / NC;
        int cx = LO + (c % NC)*4;
        int base = ry*RS + (cx-2);
        float4 A = *(const float4*)(sS + base);
        float4 B = *(const float4*)(sS + base + 4);
        uint u0 = *(const uint*)(sU + base);
        uint u1 = *(const uint*)(sU + base + 4);
        float v0 = (u0 & 0x000000FFu) ? 0.f : A.x;
        float v1 = (u0 & 0x0000FF00u) ? 0.f : A.y;
        float v2 = (u0 & 0x00FF0000u) ? 0.f : A.z;
        float v3 = (u0 & 0xFF000000u) ? 0.f : A.w;
        float v4 = (u1 & 0x000000FFu) ? 0.f : B.x;
        float v5 = (u1 & 0x0000FF00u) ? 0.f : B.y;
        float v6 = (u1 & 0x00FF0000u) ? 0.f : B.z;
        float v7 = (u1 & 0xFF000000u) ? 0.f : B.w;
        float m12 = fmaxf(v1, v2);
        float m34 = fmaxf(v3, v4);
        float m56 = fmaxf(v5, v6);
        float* q = dst + ry*RS + cx;
        *(float2*)q     = make_float2(fmaxf(fmaxf(v0, m12), m34),
                                      fmaxf(fmaxf(m12, m34), v5));
        *(float2*)(q+2) = make_float2(fmaxf(fmaxf(v2, m34), m56),
                                      fmaxf(fmaxf(m34, m56), v7));
    }
}

template<int LO>
__device__ __forceinline__ void hmax_b4(const unsigned char* __restrict__ src,
                                        unsigned char* __restrict__ dst, int tid) {
    static_assert((LO & 3) == 0, "alignment");
    constexpr int Wd = RS - 2*LO;
    constexpr int NC = Wd/4;
    constexpr int YN = Wd + 4;
    for (int c = tid; c < YN*NC; c += NT) {
        int ry = (LO-2) + c / NC;
        int cx = LO + (c % NC)*4;
        int base = ry*RS + cx;
        uint W0 = *(const uint*)(src + base - 4);
        uint W1 = *(const uint*)(src + base);
        uint W2 = *(const uint*)(src + base + 4);
        uint v1 = __byte_perm(W0, W1, 0x5432);
        uint v2 = __byte_perm(W0, W1, 0x6543);
        uint v4 = __byte_perm(W1, W2, 0x4321);
        uint v5 = __byte_perm(W1, W2, 0x5432);
        *(uint*)(dst + base) = v1 | v2 | W1 | v4 | v5;
    }
}

#define VLOAD8_F4(tp) \
    float4 t0 = *(const float4*)(tp); \
    float4 t1 = *(const float4*)((tp) + RS); \
    float4 t2 = *(const float4*)((tp) + 2*RS); \
    float4 t3 = *(const float4*)((tp) + 3*RS); \
    float4 t4 = *(const float4*)((tp) + 4*RS); \
    float4 t5 = *(const float4*)((tp) + 5*RS); \
    float4 t6 = *(const float4*)((tp) + 6*RS); \
    float4 t7 = *(const float4*)((tp) + 7*RS); \
    float4 m12 = f4max(t1,t2), m34 = f4max(t3,t4), m56 = f4max(t5,t6); \
    float4 o[4]; \
    o[0] = f4max(f4max(t0,m12),m34); \
    o[1] = f4max(f4max(m12,m34),t5); \
    o[2] = f4max(f4max(t2,m34),m56); \
    o[3] = f4max(f4max(m34,m56),t7);

__global__ __launch_bounds__(NT, 3) void nms_fused(const float* __restrict__ S) {
    extern __shared__ float sh[];
    float* sS = sh;
    float* sT = sh + RS2;
    unsigned char* sTb = (unsigned char*)sT;
    unsigned char* sM = (unsigned char*)(sh + 2*RS2);
    unsigned char* sU = sM + RS2;
    ull* sList = (ull*)(sM + 2*RS2);
    __shared__ int s_cnt, s_base;

    int tid = threadIdx.x;
    int b = blockIdx.z;
    int tx0 = blockIdx.x*64 - 10, ty0 = blockIdx.y*64 - 10;
    const float* img = S + (size_t)b*NPIX;

    bool interior = (blockIdx.x >= 1) & (blockIdx.x <= 14) &
                    (blockIdx.y >= 1) & (blockIdx.y <= 14);
    if (interior) {
        const float* rowbase = img + (size_t)ty0*W + (tx0 - 2);
        for (int i = tid; i < 84*22; i += NT) {
            int ry = i / 22, k = i - ry*22;
            float4 v = __ldg((const float4*)(rowbase + (size_t)ry*W) + k);
            int rx0 = 4*k - 2;
            float* q = sS + ry*RS + rx0;
            if (k > 0)  *(float2*)q     = make_float2(v.x, v.y);
            if (k < 21) *(float2*)(q+2) = make_float2(v.z, v.w);
        }
    } else {
        for (int i = tid; i < RS2; i += NT) {
            int ry = i/RS, rx = i - ry*RS;
            int gx = tx0+rx, gy = ty0+ry;
            bool in = ((unsigned)gx < W) & ((unsigned)gy < H);
            sS[i] = in ? __ldg(img + gy*W + gx) : 0.f;
        }
    }
    if (tid == 0) s_cnt = 0;
    __syncthreads();

    // ---- stage 1
    hmax_f4<2>(sS, sT, tid); __syncthreads();
    {
        constexpr int NCX = 21, NRY = 20;
        for (int c = tid; c < NCX*NRY; c += NT) {
            int rx0 = (c % NCX)*4;
            int ry0 = 2 + (c / NCX)*4;
            const float* tp = sT + (ry0-2)*RS + rx0;
            VLOAD8_F4(tp);
            int gx = tx0 + rx0;
            bool in0 = (unsigned)(gx+0) < W, in1 = (unsigned)(gx+1) < W;
            bool in2 = (unsigned)(gx+2) < W, in3 = (unsigned)(gx+3) < W;
            #pragma unroll
            for (int r = 0; r < 4; r++) {
                int idx = (ry0+r)*RS + rx0;
                float4 s = *(const float4*)(sS + idx);
                bool iny = (unsigned)(ty0+ry0+r) < H;
                uchar4 mm;
                mm.x = (unsigned char)(iny & in0 & (s.x == o[r].x));
                mm.y = (unsigned char)(iny & in1 & (s.y == o[r].y));
                mm.z = (unsigned char)(iny & in2 & (s.z == o[r].z));
                mm.w = (unsigned char)(iny & in3 & (s.w == o[r].w));
                *(uchar4*)(sM + idx) = mm;
            }
        }
    }
    __syncthreads();

    // ---- stage 2
    hmax_b4<4>(sM, sTb, tid); __syncthreads();
    {
        constexpr int NCX = 19, NRY = 19;
        for (int c = tid; c < NCX*NRY; c += NT) {
            int rx0 = 4 + (c % NCX)*4;
            int ry0 = 4 + (c / NCX)*4;
            const unsigned char* tp = sTb + (ry0-2)*RS + rx0;
            uint t0 = *(const uint*)(tp);
            uint t1 = *(const uint*)(tp + RS);
            uint t2 = *(const uint*)(tp + 2*RS);
            uint t3 = *(const uint*)(tp + 3*RS);
            uint t4 = *(const uint*)(tp + 4*RS);
            uint t5 = *(const uint*)(tp + 5*RS);
            uint t6 = *(const uint*)(tp + 6*RS);
            uint t7 = *(const uint*)(tp + 7*RS);
            uint m12 = t1|t2, m34 = t3|t4, m56 = t5|t6;
            unsigned char* up = sU + ry0*RS + rx0;
            *(uint*)(up)        = t0|m12|m34;
            *(uint*)(up + RS)   = m12|m34|t5;
            *(uint*)(up + 2*RS) = t2|m34|m56;
            *(uint*)(up + 3*RS) = m34|m56|t7;
        }
    }
    __syncthreads();

    // ---- stage 3
    hmax_fm4<6>(sS, sU, sT, tid); __syncthreads();
    {
        constexpr int NCX = 19, NRY = 18;
        for (int c = tid; c < NCX*NRY; c += NT) {
            int rx0 = 4 + (c % NCX)*4;
            int ry0 = 6 + (c / NCX)*4;
            const float* tp = sT + (ry0-2)*RS + rx0;
            VLOAD8_F4(tp);
            int gx = tx0 + rx0;
            bool in0 = (unsigned)(gx+0) < W, in1 = (unsigned)(gx+1) < W;
            bool in2 = (unsigned)(gx+2) < W, in3 = (unsigned)(gx+3) < W;
            #pragma unroll
            for (int r = 0; r < 4; r++) {
                int idx = (ry0+r)*RS + rx0;
                float4 s = *(const float4*)(sS + idx);
                uint u = *(const uint*)(sU + idx);
                uchar4 pm = *(const uchar4*)(sM + idx);
                bool iny = (unsigned)(ty0+ry0+r) < H;
                bool u0 = (u & 0x000000FFu) != 0, u1 = (u & 0x0000FF00u) != 0;
                bool u2 = (u & 0x00FF0000u) != 0, u3 = (u & 0xFF000000u) != 0;
                uchar4 mm;
                mm.x = (unsigned char)(iny & in0 & ((pm.x != 0) | (!u0 & (s.x == o[r].x))));
                mm.y = (unsigned char)(iny & in1 & ((pm.y != 0) | (!u1 & (s.y == o[r].y))));
                mm.z = (unsigned char)(iny & in2 & ((pm.z != 0) | (!u2 & (s.z == o[r].z))));
                mm.w = (unsigned char)(iny & in3 & ((pm.w != 0) | (!u3 & (s.w == o[r].w))));
                *(uchar4*)(sM + idx) = mm;
            }
        }
    }
    __syncthreads();

    // ---- stage 4
    hmax_b4<8>(sM, sTb, tid); __syncthreads();
    {
        constexpr int NCX = 17, NRY = 17;
        for (int c = tid; c < NCX*NRY; c += NT) {
            int rx0 = 8 + (c % NCX)*4;
            int ry0 = 8 + (c / NCX)*4;
            const unsigned char* tp = sTb + (ry0-2)*RS + rx0;
            uint t0 = *(const uint*)(tp);
            uint t1 = *(const uint*)(tp + RS);
            uint t2 = *(const uint*)(tp + 2*RS);
            uint t3 = *(const uint*)(tp + 3*RS);
            uint t4 = *(const uint*)(tp + 4*RS);
            uint t5 = *(const uint*)(tp + 5*RS);
            uint t6 = *(const uint*)(tp + 6*RS);
            uint t7 = *(const uint*)(tp + 7*RS);
            uint m12 = t1|t2, m34 = t3|t4, m56 = t5|t6;
            unsigned char* up = sU + ry0*RS + rx0;
            *(uint*)(up)        = t0|m12|m34;
            *(uint*)(up + RS)   = m12|m34|t5;
            *(uint*)(up + 2*RS) = t2|m34|m56;
            *(uint*)(up + 3*RS) = m34|m56|t7;
        }
    }
    __syncthreads();

    // ---- stage 5
    hmax_fm4<10>(sS, sU, sT, tid); __syncthreads();
    {
        constexpr int NCX = 17, NRY = 16;
        for (int c = tid; c < NCX*NRY; c += NT) {
            int rx0 = 8 + (c % NCX)*4;
            int ry0 = 10 + (c / NCX)*4;
            const float* tp = sT + (ry0-2)*RS + rx0;
            VLOAD8_F4(tp);
            #pragma unroll
            for (int r = 0; r < 4; r++) {
                int idx = (ry0+r)*RS + rx0;
                float4 s = *(const float4*)(sS + idx);
                uint u = *(const uint*)(sU + idx);
                uchar4 pm = *(const uchar4*)(sM + idx);
                int gy = ty0 + ry0 + r;
                bool by = (gy < 2) | (gy >= H-2);
                float sv[4] = {s.x, s.y, s.z, s.w};
                float ov[4] = {o[r].x, o[r].y, o[r].z, o[r].w};
                unsigned char uv[4] = {(unsigned char)(u & 0xFF),
                                       (unsigned char)((u >> 8) & 0xFF),
                                       (unsigned char)((u >> 16) & 0xFF),
                                       (unsigned char)((u >> 24) & 0xFF)};
                unsigned char pv[4] = {pm.x, pm.y, pm.z, pm.w};
                #pragma unroll
                for (int lx = 0; lx < 4; lx++) {
                    int rx = rx0 + lx;
                    if (rx < 10 || rx >= 74) continue;
                    bool ux = uv[lx] != 0;
                    bool nw = !ux && (sv[lx] == ov[lx]);
                    bool m = (pv[lx] != 0) || nw;
                    int gx = tx0 + rx;
                    bool border = (gx < 2) | (gx >= W-2) | by;
                    if (m & !border & (sv[lx] > 0.f)) {
                        unsigned ub = __float_as_uint(sv[lx]);
                        atomicAdd(&g_hist[b*NBIN + val_bin(ub)], 1u);
                        ull key = ((ull)ub << 32) |
                                  (ull)(0xFFFFFFFFu - (unsigned)(gy*W + gx));
                        int p = atomicAdd(&s_cnt, 1);
                        if (p < LISTCAP) sList[p] = key;
                        else {
                            int q = atomicAdd(&g_ccnt[b], 1);
                            if (q < CAP) g_ckey[(size_t)b*CAP + q] = key;
                        }
                    }
                }
            }
        }
        __syncthreads();
        if (tid == 0) {
            int c2 = s_cnt < LISTCAP ? s_cnt : LISTCAP;
            s_base = atomicAdd(&g_ccnt[b], c2);
            s_cnt = c2;
        }
        __syncthreads();
        int c2 = s_cnt, base = s_base;
        for (int i = tid; i < c2; i += NT) {
            int q = base + i;
            if (q < CAP) g_ckey[(size_t)b*CAP + q] = sList[i];
        }
    }
}

// ---------------- prefilter: chip-parallel threshold + direct bin-scatter to g_comp ----
__global__ void __launch_bounds__(256) prefilter_kernel() {
    __shared__ unsigned suf[NBIN];
    __shared__ unsigned swsuf[9];
    __shared__ int s_binlo, s_flag;
    __shared__ unsigned s_sel;
    int b = blockIdx.y, slice = blockIdx.x;
    int tid = threadIdx.x, lane = tid & 31, warp = tid >> 5;

    if (tid == 0) { s_binlo = -1; s_flag = 0; s_sel = 0; swsuf[8] = 0; }
    __syncthreads();

    unsigned h[16];
    const uint4* hp = (const uint4*)(g_hist + b*NBIN) + tid*4;
    #pragma unroll
    for (int q = 0; q < 4; q++) {
        uint4 w = hp[q];
        h[q*4+0]=w.x; h[q*4+1]=w.y; h[q*4+2]=w.z; h[q*4+3]=w.w;
    }
    unsigned ls[16];
    ls[15] = h[15];
    #pragma unroll
    for (int j = 14; j >= 0; j--) ls[j] = h[j] + ls[j+1];
    unsigned tt = ls[0];
    unsigned v = tt;
    #pragma unroll
    for (int o = 1; o < 32; o <<= 1) {
        unsigned t2 = __shfl_down_sync(0xFFFFFFFFu, v, o);
        if (lane + o < 32) v += t2;
    }
    if (lane == 0) swsuf[warp] = v;
    __syncthreads();
    if (warp == 0 && lane < 8) {
        unsigned wv = swsuf[lane];
        #pragma unroll
        for (int o = 1; o < 8; o <<= 1) {
            unsigned t2 = __shfl_down_sync(0x000000FFu, wv, o);
            if (lane + o < 8) wv += t2;
        }
        swsuf[lane] = wv;
    }
    __syncthreads();
    unsigned total = swsuf[0];
    unsigned tail = (v - tt) + swsuf[warp+1];
    unsigned need = total < (unsigned)TOPK ? total : (unsigned)TOPK;
    #pragma unroll
    for (int j = 0; j < 16; j++) suf[tid*16+j] = ls[j] + tail;

    if (total > (unsigned)CCAP) {
        unsigned running = tail;
        #pragma unroll
        for (int j = 15; j >= 0; j--) {
            unsigned sj = running + h[j];
            if (sj >= need && running < need) { s_binlo = tid*16+j; s_sel = sj; }
            running = sj;
        }
    } else {
        if (tid == 0) s_flag = 1;
    }
    __syncthreads();
    int binlo = s_binlo;
    if ((binlo <= 0 || s_sel > (unsigned)CCAP) && !s_flag) s_flag = 1;
    #pragma unroll
    for (int j = 0; j < 16; j++)
        if (tid*16+j >= binlo && binlo > 0 && h[j] > (unsigned)WSCR) s_flag = 1;
    __syncthreads();

    if (s_flag) {
        if (slice == 0 && tid == 0) g_flag[b] = 1;
        return;
    }
    if (slice == 0 && tid == 0) { g_flag[b] = 0; g_binlo[b] = binlo; }

    // scatter slice survivors directly into final bin-sorted g_comp positions
    int n = g_ccnt[b]; if (n > CAP) n = CAP;
    const ull* ck = g_ckey + (size_t)b*CAP;
    unsigned ulo = 0x3F000000u + ((unsigned)binlo << 11);
    int npair = n >> 1;
    int chunk = (npair + NSLICE - 1) / NSLICE;
    int lo = slice*chunk;
    int hi = min(npair, lo + chunk);
    const ulonglong2* ck2 = (const ulonglong2*)ck;
    for (int i = lo + tid; i < hi; i += 256) {
        ulonglong2 kp = ck2[i];
        #pragma unroll
        for (int s2 = 0; s2 < 2; s2++) {
            ull kk = s2 ? kp.y : kp.x;
            unsigned ua = (unsigned)(kk >> 32);
            if (ua >= ulo) {
                int bin = val_bin(ua);
                unsigned base = (bin < NBIN-1) ? suf[bin+1] : 0u;
                unsigned pos = base + atomicAdd(&g_binpos[b*NBIN + bin], 1u);
                if (pos < (unsigned)SORTN) g_comp[(size_t)b*SORTN + pos] = kk;
            }
        }
    }
    if (slice == NSLICE-1 && tid == 0 && (n & 1)) {
        ull kk = ck[n-1];
        unsigned ua = (unsigned)(kk >> 32);
        if (ua >= ulo) {
            int bin = val_bin(ua);
            unsigned base = (bin < NBIN-1) ? suf[bin+1] : 0u;
            unsigned pos = base + atomicAdd(&g_binpos[b*NBIN + bin], 1u);
            if (pos < (unsigned)SORTN) g_comp[(size_t)b*SORTN + pos] = kk;
        }
    }
}

// ---------------- binsort: warp-per-bin sorts (+ exact fallback) + state resets ----
__global__ void __launch_bounds__(1024) binsort_kernel() {
    extern __shared__ char smraw[];
    unsigned* hist = (unsigned*)smraw;          // NBIN (fallback: read-only hist unused)
    unsigned* suf  = hist + NBIN;               // NBIN (fallback: fhist)
    ull* big       = (ull*)(suf + NBIN);        // 64KB: wscr (32*256) / fallback keys (8192)

    __shared__ int s_binhi;
    __shared__ unsigned s_wsuf[33];
    __shared__ ull s_hi;
    __shared__ int s_need2, s_bin2, s_cnt2;

    int b = blockIdx.x, tid = threadIdx.x;
    int lane = tid & 31, warp = tid >> 5;
    int n = g_ccnt[b]; if (n > CAP) n = CAP;
    int flag = g_flag[b];
    int binlo = g_binlo[b];
    const ull* ck = g_ckey + (size_t)b*CAP;

    if (tid == 0) { s_binhi = 0; s_wsuf[32] = 0; }
    __syncthreads();

    uint4 hv = *((const uint4*)(g_hist + b*NBIN) + tid);
    unsigned h[4] = {hv.x, hv.y, hv.z, hv.w};
    unsigned l[4];
    l[3] = h[3]; l[2] = h[2]+l[3]; l[1] = h[1]+l[2]; l[0] = h[0]+l[1];
    #pragma unroll
    for (int k = 0; k < 4; k++) hist[tid*4+k] = h[k];
    int mybh = -1;
    #pragma unroll
    for (int k = 0; k < 4; k++) if (h[k]) mybh = tid*4+k;
    if (mybh >= 0) atomicMax(&s_binhi, mybh);

    unsigned v = l[0];
    #pragma unroll
    for (int o = 1; o < 32; o <<= 1) {
        unsigned t = __shfl_down_sync(0xFFFFFFFFu, v, o);
        if (lane + o < 32) v += t;
    }
    if (lane == 0) s_wsuf[warp] = v;
    __syncthreads();
    if (warp == 0) {
        unsigned wv = s_wsuf[lane];
        #pragma unroll
        for (int o = 1; o < 32; o <<= 1) {
            unsigned t = __shfl_down_sync(0xFFFFFFFFu, wv, o);
            if (lane + o < 32) wv += t;
        }
        s_wsuf[lane] = wv;
    }
    __syncthreads();
    unsigned tail = (v - l[0]) + s_wsuf[warp+1];
    #pragma unroll
    for (int k = 0; k < 4; k++) suf[tid*4+k] = l[k] + tail;
    __syncthreads();

    if (!flag) {
        ull* wscr = big + warp*WSCR;
        int binhi = s_binhi;
        ull* gc = g_comp + (size_t)b*SORTN;
        for (int bin = binlo + warp; bin <= binhi; bin += 32) {
            int c = (int)hist[bin];
            if (c < 2) continue;
            int start = (int)((bin < NBIN-1) ? suf[bin+1] : 0u);
            if (start >= TOPK) continue;
            int P = 1; while (P < c) P <<= 1;
            for (int i = lane; i < P; i += 32) wscr[i] = (i < c) ? gc[start+i] : 0ULL;
            __syncwarp();
            for (int k2 = 2; k2 <= P; k2 <<= 1) {
                for (int j = k2 >> 1; j > 0; j >>= 1) {
                    for (int t = lane; t < P; t += 32) {
                        int p = t ^ j;
                        if (p > t) {
                            ull a = wscr[t], c2 = wscr[p];
                            bool desc = ((t & k2) == 0);
                            if ((a < c2) == desc) { wscr[t] = c2; wscr[p] = a; }
                        }
                    }
                    __syncwarp();
                }
            }
            for (int i = lane; i < c; i += 32) gc[start+i] = wscr[i];
            __syncwarp();
        }
    } else {
        // ---- fallback: exact 6-level radix select + bitonic ----
        unsigned* fhist = suf;
        ull* keys = big;
        if (tid == 0) { s_hi = 0ull; s_need2 = TOPK; }
        __syncthreads();
        const int shifts[6] = {53, 42, 32, 21, 10, 0};
        const int nbits [6] = {11, 11, 10, 11, 11, 10};
        for (int lvl = 0; lvl < 6; lvl++) {
            int nb = nbits[lvl], sh2 = shifts[lvl], nbin = 1 << nb;
            for (int i = tid; i < nbin; i += 1024) fhist[i] = 0;
            __syncthreads();
            ull hi = s_hi;
            for (int i = tid; i < n; i += 1024) {
                ull c = ck[i];
                if ((c >> (sh2 + nb)) == hi)
                    atomicAdd(&fhist[(unsigned)((c >> sh2) & (ull)(nbin-1))], 1u);
            }
            __syncthreads();
            for (int o = 1; o < nbin; o <<= 1) {
                unsigned a0 = 0, a1 = 0;
                int i0 = tid, i1 = tid + 1024;
                if (i0 < nbin) a0 = fhist[i0] + ((i0+o < nbin) ? fhist[i0+o] : 0u);
                if (i1 < nbin) a1 = fhist[i1] + ((i1+o < nbin) ? fhist[i1+o] : 0u);
                __syncthreads();
                if (i0 < nbin) fhist[i0] = a0;
                if (i1 < nbin) fhist[i1] = a1;
                __syncthreads();
            }
            if (tid == 0) s_bin2 = -1;
            __syncthreads();
            int need2 = s_need2;
            for (int i = tid; i < nbin; i += 1024) {
                unsigned Si = fhist[i];
                unsigned Sn = (i+1 < nbin) ? fhist[i+1] : 0u;
                if (Si >= (unsigned)need2 && Sn < (unsigned)need2) s_bin2 = i;
            }
            __syncthreads();
            if (tid == 0) {
                int bin = s_bin2;
                if (bin < 0) { bin = 0; s_need2 = (int)fhist[0]; }
                else {
                    unsigned above = (bin+1 < nbin) ? fhist[bin+1] : 0u;
                    s_need2 = s_need2 - (int)above;
                }
                s_hi = (s_hi << nb) | (ull)(unsigned)bin;
            }
            __syncthreads();
        }
        ull T = s_hi;
        if (tid == 0) s_cnt2 = 0;
        __syncthreads();
        for (int i = tid; i < n; i += 1024) {
            ull c = ck[i];
            if (c >= T) {
                int p = atomicAdd(&s_cnt2, 1);
                if (p < TOPK) keys[p] = c;
            }
        }
        __syncthreads();
        int cnt2 = s_cnt2; if (cnt2 > TOPK) cnt2 = TOPK;
        for (int i = tid; i < TOPK; i += 1024)
            if (i >= cnt2) keys[i] = (ull)(0xFFFFFFFFu - (unsigned)i);
        __syncthreads();
        for (int k = 2; k <= TOPK; k <<= 1) {
            for (int j = k >> 1; j > 0; j >>= 1) {
                for (int t = tid; t < TOPK; t += 1024) {
                    int p = t ^ j;
                    if (p > t) {
                        ull a = keys[t], c2 = keys[p];
                        bool asc = ((t & k) == 0);
                        if ((a > c2) == asc) { keys[t] = c2; keys[p] = a; }
                    }
                }
                __syncthreads();
            }
        }
        for (int i = tid; i < TOPK; i += 1024)
            g_comp[(size_t)b*SORTN + i] = keys[TOPK-1-i];
    }

    // ---- state resets for next graph replay ----
    *((uint4*)(g_hist + b*NBIN) + tid)   = make_uint4(0,0,0,0);
    *((uint4*)(g_binpos + b*NBIN) + tid) = make_uint4(0,0,0,0);
    if (tid == 0) g_ccnt[b] = 0;
}

// ---------------- refinement ----------------
__device__ __forceinline__ float bil_tap(const float* img, float xf, float yf, float wgt) {
    bool valid = (xf >= 0.f) & (xf < (float)W) & (yf >= 0.f) & (yf < (float)H);
    int xc = (int)fminf(fmaxf(xf, 0.f), (float)(W-1));
    int yc = (int)fminf(fmaxf(yf, 0.f), (float)(H-1));
    float s = valid ? img[yc*W + xc] : 0.f;
    return s * wgt;
}

__global__ void refine_kernel(const float* __restrict__ S, float* __restrict__ out) {
    int g = blockIdx.x * blockDim.x + threadIdx.x;
    if (g >= BATCH*TOPK) return;
    int b = g / TOPK;
    int i = g - b*TOPK;
    ull key = g_comp[(size_t)b*SORTN + i];
    int idx = (int)(0xFFFFFFFFu - (unsigned)(key & 0xFFFFFFFFull));
    int ix = idx & (W-1), iy = idx >> 10;
    const float* img = S + (size_t)b*NPIX;

    float v[25];
    float mx = -1e30f;
    #pragma unroll
    for (int dy = 0; dy < 5; dy++) {
        int y = iy + dy - 2;
        #pragma unroll
        for (int dx = 0; dx < 5; dx++) {
            int x = ix + dx - 2;
            float val = (y >= 0 && y < H && x >= 0 && x < W) ? __ldg(img + y*W + x) : 0.f;
            v[dy*5 + dx] = val;
            mx = fmaxf(mx, val);
        }
    }
    float e[25];
    float S0 = 0.f, Sx = 0.f, Sy = 0.f;
    #pragma unroll
    for (int p = 0; p < 25; p++) {
        float ee = expf((v[p] - mx) * 10.0f);
        e[p] = ee;
        S0 += ee;
        Sx += ee * (float)(p % 5 - 2);
        Sy += ee * (float)(p / 5 - 2);
    }
    float rx = Sx / S0, ry = Sy / S0;
    float disp = 0.f;
    #pragma unroll
    for (int p = 0; p < 25; p++) {
        float ddx = ((float)(p % 5 - 2) - rx) * 0.5f;
        float ddy = ((float)(p / 5 - 2) - ry) * 0.5f;
        disp += e[p] * (ddx*ddx + ddy*ddy);
    }
    disp /= S0;

    float kx = ((float)ix + rx) / (float)(W-1) * 2.f - 1.f;
    float ky = ((float)iy + ry) / (float)(H-1) * 2.f - 1.f;

    float px = (kx + 1.f) * 0.5f * (float)(W-1);
    float py = (ky + 1.f) * 0.5f * (float)(H-1);
    float x0 = floorf(px), y0 = floorf(py);
    float wx1 = px - x0, wx0 = 1.f - wx1;
    float wy1 = py - y0, wy0 = 1.f - wy1;
    float score = bil_tap(img, x0,     y0,     wx0*wy0)
                + bil_tap(img, x0+1.f, y0,     wx1*wy0)
                + bil_tap(img, x0,     y0+1.f, wx0*wy1)
                + bil_tap(img, x0+1.f, y0+1.f, wx1*wy1);

    out[2*g + 0] = kx;
    out[2*g + 1] = ky;
    out[BATCH*TOPK*2 + g] = score;
    out[BATCH*TOPK*3 + g] = disp;
}

// ---------------- launch ----------------
extern "C" void kernel_launch(void* const* d_in, const int* in_sizes, int n_in,
                              void* d_out, int out_size) {
    const float* S = (const float*)d_in[0];
    float* out = (float*)d_out;

    const int nms_smem = 2*RS2*sizeof(float) + 2*RS2 + LISTCAP*sizeof(ull);
    const int bs_smem  = 2*NBIN*sizeof(unsigned) + SORTN*sizeof(ull);  // 32KB + 64KB = 98304
    static int attr_set = 0;
    if (!attr_set) {
        cudaFuncSetAttribute(nms_fused, cudaFuncAttributeMaxDynamicSharedMemorySize, nms_smem);
        cudaFuncSetAttribute(binsort_kernel, cudaFuncAttributeMaxDynamicSharedMemorySize, bs_smem);
        attr_set = 1;
    }

    dim3 grid(16, 16, 8);
    nms_fused<<<grid, NT, nms_smem>>>(S);
    prefilter_kernel<<<dim3(NSLICE, BATCH), 256>>>();
    binsort_kernel<<<BATCH, 1024, bs_smem>>>();
    refine_kernel<<<(BATCH*TOPK + 127) / 128, 128>>>(S, out);
}